// round 4
// baseline (speedup 1.0000x reference)
#include <cuda_runtime.h>
#include <cstdint>

// ---------------------------------------------------------------------------
// CategoricalGINEncoder on GB300 (sm_103a) — round 4
//   T_f = emb_f @ W1a_f ; z0 = sum_f T_f[cat_f]        (replaces embed+GEMM1)
//   conv1 (fused): gather-agg(z0) -> relu(+b1a) -> @W1b+b1b -> relu -> LN1
//                  -> @W2a -> u   (u = h@W2a hoisted before agg2: agg linear)
//   conv2 (fused): gather-agg(u) -> relu(+b2a) -> @W2b+b2b -> LN2 -> out
//  GEMM: tf32 mma.sync 64x256 tile, BK=16 DOUBLE-buffered W, 2 CTAs/SM.
//  Aggregation fused into conv (no intermediate agg buffer round-trip).
// ---------------------------------------------------------------------------

#define NMAX 100000
#define EMAX 1600000
#define DIM  256

__device__ float g_b0[(size_t)NMAX * DIM];
__device__ float g_b1[(size_t)NMAX * DIM];
__device__ float g_tab[(size_t)4 * 1024 * DIM];
__device__ int   g_deg[NMAX];
__device__ int   g_rowptr[NMAX + 1];
__device__ int   g_cursor[NMAX];
__device__ int   g_csr[EMAX];

// ------------------------------- CSR build --------------------------------

__global__ void k_zero(int* __restrict__ p, int n) {
    int i = blockIdx.x * blockDim.x + threadIdx.x;
    if (i < n) p[i] = 0;
}

__global__ void k_count(const int* __restrict__ ei, int* __restrict__ deg, int E) {
    int e = blockIdx.x * blockDim.x + threadIdx.x;
    if (e < E) atomicAdd(&deg[ei[E + e]], 1);
}

__global__ void k_scan(const int* __restrict__ deg, int* __restrict__ rowptr,
                       int* __restrict__ cursor, int n) {
    __shared__ int sh[1024];
    int t = threadIdx.x;
    int chunk = (n + 1023) >> 10;
    int lo = t * chunk;
    int hi = min(lo + chunk, n);
    int s = 0;
    for (int i = lo; i < hi; ++i) s += deg[i];
    sh[t] = s;
    __syncthreads();
    for (int off = 1; off < 1024; off <<= 1) {
        int v = (t >= off) ? sh[t - off] : 0;
        __syncthreads();
        sh[t] += v;
        __syncthreads();
    }
    int run = (t == 0) ? 0 : sh[t - 1];
    for (int i = lo; i < hi; ++i) {
        rowptr[i] = run;
        cursor[i] = run;
        run += deg[i];
    }
    if (lo < n && hi == n) rowptr[n] = run;
}

__global__ void k_fill(const int* __restrict__ ei, int* __restrict__ cursor,
                       int* __restrict__ csr, int E) {
    int e = blockIdx.x * blockDim.x + threadIdx.x;
    if (e < E) {
        int s = ei[e];
        int d = ei[E + e];
        int p = atomicAdd(&cursor[d], 1);
        csr[p] = s;
    }
}

// ------------------------ embedding tables T_f ------------------------------

__global__ void k_tab(const float* __restrict__ e0, const float* __restrict__ e1,
                      const float* __restrict__ e2, const float* __restrict__ e3,
                      const float* __restrict__ w1a, float* __restrict__ T, int V) {
    int f = blockIdx.y;
    const float* emb = (f == 0) ? e0 : (f == 1) ? e1 : (f == 2) ? e2 : e3;
    int v0 = blockIdx.x * 16;
    __shared__ float es[16 * 64];
    int tid = threadIdx.x;
    #pragma unroll
    for (int i = 0; i < 4; ++i) {
        int idx = i * 256 + tid;
        int v = idx >> 6, k = idx & 63;
        es[idx] = (v0 + v < V) ? emb[(v0 + v) * 64 + k] : 0.f;
    }
    __syncthreads();
    float acc[16];
    #pragma unroll
    for (int v = 0; v < 16; ++v) acc[v] = 0.f;
    int c = tid;
    #pragma unroll 4
    for (int k = 0; k < 64; ++k) {
        float w = w1a[(f * 64 + k) * 256 + c];
        #pragma unroll
        for (int v = 0; v < 16; ++v) acc[v] = fmaf(es[v * 64 + k], w, acc[v]);
    }
    #pragma unroll
    for (int v = 0; v < 16; ++v)
        if (v0 + v < V) T[((size_t)f * 1024 + v0 + v) * 256 + c] = acc[v];
}

__global__ void k_z0(const int* __restrict__ xc, const float* __restrict__ T,
                     float* __restrict__ Z, int M) {
    int idx = blockIdx.x * blockDim.x + threadIdx.x;
    if (idx >= M * 64) return;
    int node = idx >> 6;
    int c4 = idx & 63;
    int c0 = xc[node * 4 + 0];
    int c1 = xc[node * 4 + 1];
    int c2 = xc[node * 4 + 2];
    int c3 = xc[node * 4 + 3];
    const float4* t0 = (const float4*)(T + ((size_t)0 * 1024 + c0) * 256);
    const float4* t1 = (const float4*)(T + ((size_t)1 * 1024 + c1) * 256);
    const float4* t2 = (const float4*)(T + ((size_t)2 * 1024 + c2) * 256);
    const float4* t3 = (const float4*)(T + ((size_t)3 * 1024 + c3) * 256);
    float4 a = t0[c4], b = t1[c4], c = t2[c4], d = t3[c4];
    float4 r;
    r.x = a.x + b.x + c.x + d.x;
    r.y = a.y + b.y + c.y + d.y;
    r.z = a.z + b.z + c.z + d.z;
    r.w = a.w + b.w + c.w + d.w;
    ((float4*)(Z + (size_t)node * 256))[c4] = r;
}

// ------------------------------ fused conv ---------------------------------
// gather-agg + relu(+bias) staged to XS (tf32), then 1-2 GEMMs + LN in-block.
// 64x256 tile, 8 warps (2M x 4N), warp tile 32x64, BK=16 double-buffered W.

#define XP    260
#define XS_SZ (64 * XP)            // 16640 floats
#define WPAD  264
#define W_ST  (16 * WPAD)          // 4224 floats per chunk
#define CONV_SMEM_BYTES ((XS_SZ + 2 * W_ST) * 4)   // 100352 B -> 2 CTAs/SM

__device__ __forceinline__ float to_tf32(float x) {
    uint32_t u;
    asm("cvt.rna.tf32.f32 %0, %1;" : "=r"(u) : "f"(x));
    return __uint_as_float(u);
}

__device__ __forceinline__ void mma8(float* c, const uint32_t* a, const uint32_t* b) {
    asm volatile(
        "mma.sync.aligned.m16n8k8.row.col.f32.tf32.tf32.f32 "
        "{%0,%1,%2,%3},{%4,%5,%6,%7},{%8,%9},{%0,%1,%2,%3};\n"
        : "+f"(c[0]), "+f"(c[1]), "+f"(c[2]), "+f"(c[3])
        : "r"(a[0]), "r"(a[1]), "r"(a[2]), "r"(a[3]), "r"(b[0]), "r"(b[1]));
}

// C += XS(64x256 tf32) @ W(256x256); W via double-buffered BK=16 smem chunks.
// One __syncthreads per iteration: stores target the buffer last read at it-1,
// whose readers all passed the previous barrier.
__device__ __forceinline__ void gemm_k256(
    const float* __restrict__ W, const float* XS, float* WS,
    float (&c)[2][8][4], int tid, int wm, int wn, int g, int tq) {
    const int wq = tid & 63;
    const int wkb = tid >> 6;          // 0..3
    float4 rw[4];
    #pragma unroll
    for (int i = 0; i < 4; ++i)
        rw[i] = *(const float4*)(W + (long)(wkb + i * 4) * 256 + wq * 4);
    #pragma unroll
    for (int i = 0; i < 4; ++i) {
        float4 v = rw[i];
        v.x = to_tf32(v.x); v.y = to_tf32(v.y);
        v.z = to_tf32(v.z); v.w = to_tf32(v.w);
        *(float4*)(WS + (wkb + i * 4) * WPAD + wq * 4) = v;
    }
    __syncthreads();
    #pragma unroll 1
    for (int it = 0; it < 16; ++it) {
        if (it < 15) {
            int k0 = (it + 1) * 16;
            #pragma unroll
            for (int i = 0; i < 4; ++i)
                rw[i] = *(const float4*)(W + (long)(k0 + wkb + i * 4) * 256 + wq * 4);
        }
        const float* ws = WS + (it & 1) * W_ST;
        #pragma unroll
        for (int kt = 0; kt < 2; ++kt) {
            int kb = it * 16 + kt * 8;
            int kw = kt * 8;
            uint32_t af[2][4], bf[8][2];
            #pragma unroll
            for (int mt = 0; mt < 2; ++mt) {
                int r0 = wm * 32 + mt * 16;
                af[mt][0] = __float_as_uint(XS[(r0 + g)     * XP + kb + tq]);
                af[mt][1] = __float_as_uint(XS[(r0 + 8 + g) * XP + kb + tq]);
                af[mt][2] = __float_as_uint(XS[(r0 + g)     * XP + kb + 4 + tq]);
                af[mt][3] = __float_as_uint(XS[(r0 + 8 + g) * XP + kb + 4 + tq]);
            }
            #pragma unroll
            for (int nt = 0; nt < 8; ++nt) {
                int n0 = wn * 64 + nt * 8;
                bf[nt][0] = __float_as_uint(ws[(kw + tq)     * WPAD + n0 + g]);
                bf[nt][1] = __float_as_uint(ws[(kw + 4 + tq) * WPAD + n0 + g]);
            }
            #pragma unroll
            for (int mt = 0; mt < 2; ++mt)
                #pragma unroll
                for (int nt = 0; nt < 8; ++nt)
                    mma8(c[mt][nt], af[mt], bf[nt]);
        }
        if (it < 15) {
            float* wsN = WS + ((it + 1) & 1) * W_ST;
            #pragma unroll
            for (int i = 0; i < 4; ++i) {
                float4 v = rw[i];
                v.x = to_tf32(v.x); v.y = to_tf32(v.y);
                v.z = to_tf32(v.z); v.w = to_tf32(v.w);
                *(float4*)(wsN + (wkb + i * 4) * WPAD + wq * 4) = v;
            }
            __syncthreads();
        }
    }
}

__global__ void __launch_bounds__(256, 2) k_conv(
    const float* __restrict__ X,
    const int* __restrict__ rowptr, const int* __restrict__ csr,
    const float* __restrict__ bIn,
    const float* __restrict__ W1,  const float* __restrict__ b1,
    const float* __restrict__ lng, const float* __restrict__ lnb,
    const float* __restrict__ W2,  float* __restrict__ Out,
    int M, int reluLN, int hasG2) {
    extern __shared__ float sm[];
    float* XS = sm;
    float* WS = sm + XS_SZ;

    const int tid  = threadIdx.x;
    const int warp = tid >> 5, lane = tid & 31;
    const int wm = warp >> 2;
    const int wn = warp & 3;
    const int g  = lane >> 2;
    const int tq = lane & 3;
    const long blockRow = (long)blockIdx.x * 64;

    // ---- fused gather-agg + bias + relu -> XS (tf32) ----
    {
        const float4* bi4 = (const float4*)bIn;
        float4 bv0 = bi4[lane];
        float4 bv1 = bi4[lane + 32];
        #pragma unroll 1
        for (int i = 0; i < 8; ++i) {
            int row = warp * 8 + i;
            long grow = blockRow + row;
            float4 a0 = {0.f, 0.f, 0.f, 0.f};
            float4 a1 = {0.f, 0.f, 0.f, 0.f};
            if (grow < M) {
                const float4* xr = (const float4*)(X + grow * 256);
                a0 = xr[lane];
                a1 = xr[lane + 32];
                int e = rowptr[grow], end = rowptr[grow + 1];
                for (; e + 1 < end; e += 2) {
                    int s0 = csr[e];
                    int s1 = csr[e + 1];
                    const float4* x0 = (const float4*)(X + (size_t)s0 * 256);
                    const float4* x1 = (const float4*)(X + (size_t)s1 * 256);
                    float4 u0 = x0[lane];
                    float4 u1 = x0[lane + 32];
                    float4 v0 = x1[lane];
                    float4 v1 = x1[lane + 32];
                    a0.x += u0.x; a0.y += u0.y; a0.z += u0.z; a0.w += u0.w;
                    a1.x += u1.x; a1.y += u1.y; a1.z += u1.z; a1.w += u1.w;
                    a0.x += v0.x; a0.y += v0.y; a0.z += v0.z; a0.w += v0.w;
                    a1.x += v1.x; a1.y += v1.y; a1.z += v1.z; a1.w += v1.w;
                }
                if (e < end) {
                    int s = csr[e];
                    const float4* xs = (const float4*)(X + (size_t)s * 256);
                    float4 u0 = xs[lane];
                    float4 u1 = xs[lane + 32];
                    a0.x += u0.x; a0.y += u0.y; a0.z += u0.z; a0.w += u0.w;
                    a1.x += u1.x; a1.y += u1.y; a1.z += u1.z; a1.w += u1.w;
                }
                a0.x = to_tf32(fmaxf(a0.x + bv0.x, 0.f));
                a0.y = to_tf32(fmaxf(a0.y + bv0.y, 0.f));
                a0.z = to_tf32(fmaxf(a0.z + bv0.z, 0.f));
                a0.w = to_tf32(fmaxf(a0.w + bv0.w, 0.f));
                a1.x = to_tf32(fmaxf(a1.x + bv1.x, 0.f));
                a1.y = to_tf32(fmaxf(a1.y + bv1.y, 0.f));
                a1.z = to_tf32(fmaxf(a1.z + bv1.z, 0.f));
                a1.w = to_tf32(fmaxf(a1.w + bv1.w, 0.f));
            }
            *(float4*)(XS + row * XP + lane * 4)        = a0;
            *(float4*)(XS + row * XP + (lane + 32) * 4) = a1;
        }
    }
    // (gemm prologue's __syncthreads orders XS writes before all reads)

    float c[2][8][4];
    #pragma unroll
    for (int i = 0; i < 2; ++i)
        #pragma unroll
        for (int j = 0; j < 8; ++j)
            #pragma unroll
            for (int k = 0; k < 4; ++k) c[i][j][k] = 0.f;

    gemm_k256(W1, XS, WS, c, tid, wm, wn, g, tq);

    // ---- epilogue 1: bias (+relu) -> XS fp32 ----
    __syncthreads();
    #pragma unroll
    for (int mt = 0; mt < 2; ++mt) {
        int r0 = wm * 32 + mt * 16;
        #pragma unroll
        for (int nt = 0; nt < 8; ++nt) {
            int col = wn * 64 + nt * 8 + tq * 2;
            float2 bv = *(const float2*)(b1 + col);
            float v0 = c[mt][nt][0] + bv.x;
            float v1 = c[mt][nt][1] + bv.y;
            float v2 = c[mt][nt][2] + bv.x;
            float v3 = c[mt][nt][3] + bv.y;
            if (reluLN) {
                v0 = fmaxf(v0, 0.f); v1 = fmaxf(v1, 0.f);
                v2 = fmaxf(v2, 0.f); v3 = fmaxf(v3, 0.f);
            }
            XS[(r0 + g)     * XP + col]     = v0;
            XS[(r0 + g)     * XP + col + 1] = v1;
            XS[(r0 + 8 + g) * XP + col]     = v2;
            XS[(r0 + 8 + g) * XP + col + 1] = v3;
        }
    }
    __syncthreads();

    // ---- LayerNorm ----
    {
        float4 ga  = *(const float4*)(lng + lane * 8);
        float4 gb  = *(const float4*)(lng + lane * 8 + 4);
        float4 bta = *(const float4*)(lnb + lane * 8);
        float4 btb = *(const float4*)(lnb + lane * 8 + 4);
        #pragma unroll 1
        for (int i = 0; i < 8; ++i) {
            int row = warp * 8 + i;
            long grow = blockRow + row;
            float4 v0 = *(const float4*)(XS + row * XP + lane * 8);
            float4 v1 = *(const float4*)(XS + row * XP + lane * 8 + 4);
            float s  = v0.x + v0.y + v0.z + v0.w + v1.x + v1.y + v1.z + v1.w;
            float ss = v0.x * v0.x + v0.y * v0.y + v0.z * v0.z + v0.w * v0.w +
                       v1.x * v1.x + v1.y * v1.y + v1.z * v1.z + v1.w * v1.w;
            #pragma unroll
            for (int o = 16; o >= 1; o >>= 1) {
                s  += __shfl_xor_sync(0xffffffffu, s, o);
                ss += __shfl_xor_sync(0xffffffffu, ss, o);
            }
            float mean = s * (1.f / 256.f);
            float var  = ss * (1.f / 256.f) - mean * mean;
            float rstd = rsqrtf(var + 1e-5f);
            float4 o0, o1;
            o0.x = (v0.x - mean) * rstd * ga.x + bta.x;
            o0.y = (v0.y - mean) * rstd * ga.y + bta.y;
            o0.z = (v0.z - mean) * rstd * ga.z + bta.z;
            o0.w = (v0.w - mean) * rstd * ga.w + bta.w;
            o1.x = (v1.x - mean) * rstd * gb.x + btb.x;
            o1.y = (v1.y - mean) * rstd * gb.y + btb.y;
            o1.z = (v1.z - mean) * rstd * gb.z + btb.z;
            o1.w = (v1.w - mean) * rstd * gb.w + btb.w;
            if (hasG2) {
                o0.x = to_tf32(o0.x); o0.y = to_tf32(o0.y);
                o0.z = to_tf32(o0.z); o0.w = to_tf32(o0.w);
                o1.x = to_tf32(o1.x); o1.y = to_tf32(o1.y);
                o1.z = to_tf32(o1.z); o1.w = to_tf32(o1.w);
                *(float4*)(XS + row * XP + lane * 8)     = o0;
                *(float4*)(XS + row * XP + lane * 8 + 4) = o1;
            } else if (grow < M) {
                *(float4*)(Out + grow * 256 + lane * 8)     = o0;
                *(float4*)(Out + grow * 256 + lane * 8 + 4) = o1;
            }
        }
    }
    if (!hasG2) return;
    __syncthreads();

    // ---- GEMM2: u = h @ W2 (no bias) ----
    #pragma unroll
    for (int i = 0; i < 2; ++i)
        #pragma unroll
        for (int j = 0; j < 8; ++j)
            #pragma unroll
            for (int k = 0; k < 4; ++k) c[i][j][k] = 0.f;

    gemm_k256(W2, XS, WS, c, tid, wm, wn, g, tq);

    #pragma unroll
    for (int mt = 0; mt < 2; ++mt) {
        long rb = blockRow + wm * 32 + mt * 16;
        long r0 = rb + g;
        long r1 = rb + 8 + g;
        #pragma unroll
        for (int nt = 0; nt < 8; ++nt) {
            int col = wn * 64 + nt * 8 + tq * 2;
            if (r0 < M) {
                float2 t = {c[mt][nt][0], c[mt][nt][1]};
                *(float2*)(Out + r0 * 256 + col) = t;
            }
            if (r1 < M) {
                float2 t = {c[mt][nt][2], c[mt][nt][3]};
                *(float2*)(Out + r1 * 256 + col) = t;
            }
        }
    }
}

// --------------------------------- driver ---------------------------------

extern "C" void kernel_launch(void* const* d_in, const int* in_sizes, int n_in,
                              void* d_out, int out_size) {
    const int*   xcat = (const int*)d_in[0];
    const int*   ei   = (const int*)d_in[1];
    const float* e0   = (const float*)d_in[2];
    const float* e1   = (const float*)d_in[3];
    const float* e2   = (const float*)d_in[4];
    const float* e3   = (const float*)d_in[5];
    const float* w1a  = (const float*)d_in[6];
    const float* b1a  = (const float*)d_in[7];
    const float* w1b  = (const float*)d_in[8];
    const float* b1b  = (const float*)d_in[9];
    const float* w2a  = (const float*)d_in[10];
    const float* b2a  = (const float*)d_in[11];
    const float* w2b  = (const float*)d_in[12];
    const float* b2b  = (const float*)d_in[13];
    const float* ln1g = (const float*)d_in[14];
    const float* ln1b = (const float*)d_in[15];
    const float* ln2g = (const float*)d_in[16];
    const float* ln2b = (const float*)d_in[17];

    int M = in_sizes[0] / 4;
    int E = in_sizes[1] / 2;
    int V = in_sizes[2] / 64;

    float *b0, *b1, *tab;
    int *deg, *rowptr, *cursor, *csr;
    cudaGetSymbolAddress((void**)&b0, g_b0);
    cudaGetSymbolAddress((void**)&b1, g_b1);
    cudaGetSymbolAddress((void**)&tab, g_tab);
    cudaGetSymbolAddress((void**)&deg, g_deg);
    cudaGetSymbolAddress((void**)&rowptr, g_rowptr);
    cudaGetSymbolAddress((void**)&cursor, g_cursor);
    cudaGetSymbolAddress((void**)&csr, g_csr);

    cudaFuncSetAttribute(k_conv, cudaFuncAttributeMaxDynamicSharedMemorySize,
                         CONV_SMEM_BYTES);

    int convGrid = (M + 63) / 64;

    // CSR by dst
    k_zero<<<(M + 255) / 256, 256>>>(deg, M);
    k_count<<<(E + 255) / 256, 256>>>(ei, deg, E);
    k_scan<<<1, 1024>>>(deg, rowptr, cursor, M);
    k_fill<<<(E + 255) / 256, 256>>>(ei, cursor, csr, E);

    // tables + z0
    dim3 tgrid((V + 15) / 16, 4);
    k_tab<<<tgrid, 256>>>(e0, e1, e2, e3, w1a, tab, V);
    k_z0<<<(M * 64 + 255) / 256, 256>>>(xcat, tab, b0, M);

    // conv1 (fused agg): gather b0 -> ... -> u into b1
    k_conv<<<convGrid, 256, CONV_SMEM_BYTES>>>(b0, rowptr, csr, b1a,
                                               w1b, b1b, ln1g, ln1b,
                                               w2a, b1, M, 1, 1);

    // conv2 (fused agg): gather b1 -> ... -> out
    k_conv<<<convGrid, 256, CONV_SMEM_BYTES>>>(b1, rowptr, csr, b2a,
                                               w2b, b2b, ln2g, ln2b,
                                               nullptr, (float*)d_out, M, 0, 0);
}

// round 5
// speedup vs baseline: 1.0931x; 1.0931x over previous
#include <cuda_runtime.h>
#include <cstdint>

// ---------------------------------------------------------------------------
// CategoricalGINEncoder on GB300 (sm_103a) — round 5
//  = round 3 structure (standalone warp-per-row agg; fused conv MLP+LN)
//  + double-buffered W chunks in gemm_k256 (BK=16, one barrier/iter, 2 CTAs/SM)
//   T_f = emb_f @ W1a_f ; z0 = sum_f T_f[cat_f]
//   a1 = agg(z0); conv1: relu(+b1a) -> @W1b+b1b -> relu -> LN1 -> @W2a -> u
//   a2 = agg(u);  conv2: relu(+b2a) -> @W2b+b2b -> LN2 -> out
// ---------------------------------------------------------------------------

#define NMAX 100000
#define EMAX 1600000
#define DIM  256

__device__ float g_b0[(size_t)NMAX * DIM];
__device__ float g_b1[(size_t)NMAX * DIM];
__device__ float g_tab[(size_t)4 * 1024 * DIM];
__device__ int   g_deg[NMAX];
__device__ int   g_rowptr[NMAX + 1];
__device__ int   g_cursor[NMAX];
__device__ int   g_csr[EMAX];

// ------------------------------- CSR build --------------------------------

__global__ void k_zero(int* __restrict__ p, int n) {
    int i = blockIdx.x * blockDim.x + threadIdx.x;
    if (i < n) p[i] = 0;
}

__global__ void k_count(const int* __restrict__ ei, int* __restrict__ deg, int E) {
    int e = blockIdx.x * blockDim.x + threadIdx.x;
    if (e < E) atomicAdd(&deg[ei[E + e]], 1);
}

__global__ void k_scan(const int* __restrict__ deg, int* __restrict__ rowptr,
                       int* __restrict__ cursor, int n) {
    __shared__ int sh[1024];
    int t = threadIdx.x;
    int chunk = (n + 1023) >> 10;
    int lo = t * chunk;
    int hi = min(lo + chunk, n);
    int s = 0;
    for (int i = lo; i < hi; ++i) s += deg[i];
    sh[t] = s;
    __syncthreads();
    for (int off = 1; off < 1024; off <<= 1) {
        int v = (t >= off) ? sh[t - off] : 0;
        __syncthreads();
        sh[t] += v;
        __syncthreads();
    }
    int run = (t == 0) ? 0 : sh[t - 1];
    for (int i = lo; i < hi; ++i) {
        rowptr[i] = run;
        cursor[i] = run;
        run += deg[i];
    }
    if (lo < n && hi == n) rowptr[n] = run;
}

__global__ void k_fill(const int* __restrict__ ei, int* __restrict__ cursor,
                       int* __restrict__ csr, int E) {
    int e = blockIdx.x * blockDim.x + threadIdx.x;
    if (e < E) {
        int s = ei[e];
        int d = ei[E + e];
        int p = atomicAdd(&cursor[d], 1);
        csr[p] = s;
    }
}

// ------------------------ embedding tables T_f ------------------------------

__global__ void k_tab(const float* __restrict__ e0, const float* __restrict__ e1,
                      const float* __restrict__ e2, const float* __restrict__ e3,
                      const float* __restrict__ w1a, float* __restrict__ T, int V) {
    int f = blockIdx.y;
    const float* emb = (f == 0) ? e0 : (f == 1) ? e1 : (f == 2) ? e2 : e3;
    int v0 = blockIdx.x * 16;
    __shared__ float es[16 * 64];
    int tid = threadIdx.x;
    #pragma unroll
    for (int i = 0; i < 4; ++i) {
        int idx = i * 256 + tid;
        int v = idx >> 6, k = idx & 63;
        es[idx] = (v0 + v < V) ? emb[(v0 + v) * 64 + k] : 0.f;
    }
    __syncthreads();
    float acc[16];
    #pragma unroll
    for (int v = 0; v < 16; ++v) acc[v] = 0.f;
    int c = tid;
    #pragma unroll 4
    for (int k = 0; k < 64; ++k) {
        float w = w1a[(f * 64 + k) * 256 + c];
        #pragma unroll
        for (int v = 0; v < 16; ++v) acc[v] = fmaf(es[v * 64 + k], w, acc[v]);
    }
    #pragma unroll
    for (int v = 0; v < 16; ++v)
        if (v0 + v < V) T[((size_t)f * 1024 + v0 + v) * 256 + c] = acc[v];
}

__global__ void k_z0(const int* __restrict__ xc, const float* __restrict__ T,
                     float* __restrict__ Z, int M) {
    int idx = blockIdx.x * blockDim.x + threadIdx.x;
    if (idx >= M * 64) return;
    int node = idx >> 6;
    int c4 = idx & 63;
    int c0 = xc[node * 4 + 0];
    int c1 = xc[node * 4 + 1];
    int c2 = xc[node * 4 + 2];
    int c3 = xc[node * 4 + 3];
    const float4* t0 = (const float4*)(T + ((size_t)0 * 1024 + c0) * 256);
    const float4* t1 = (const float4*)(T + ((size_t)1 * 1024 + c1) * 256);
    const float4* t2 = (const float4*)(T + ((size_t)2 * 1024 + c2) * 256);
    const float4* t3 = (const float4*)(T + ((size_t)3 * 1024 + c3) * 256);
    float4 a = t0[c4], b = t1[c4], c = t2[c4], d = t3[c4];
    float4 r;
    r.x = a.x + b.x + c.x + d.x;
    r.y = a.y + b.y + c.y + d.y;
    r.z = a.z + b.z + c.z + d.z;
    r.w = a.w + b.w + c.w + d.w;
    ((float4*)(Z + (size_t)node * 256))[c4] = r;
}

// --------------------------- aggregation (GIN) ----------------------------
// warp per row, unroll-2 prefetch

__global__ void k_agg(const float* __restrict__ X, float* __restrict__ Y,
                      const int* __restrict__ rowptr, const int* __restrict__ csr,
                      int M) {
    int w = (blockIdx.x * blockDim.x + threadIdx.x) >> 5;
    int lane = threadIdx.x & 31;
    if (w >= M) return;
    const float4* xr = (const float4*)(X + (size_t)w * DIM);
    float4 a0 = xr[lane];
    float4 a1 = xr[lane + 32];
    int e = rowptr[w], end = rowptr[w + 1];
    for (; e + 1 < end; e += 2) {
        int s0 = csr[e];
        int s1 = csr[e + 1];
        const float4* x0 = (const float4*)(X + (size_t)s0 * DIM);
        const float4* x1 = (const float4*)(X + (size_t)s1 * DIM);
        float4 u0 = x0[lane];
        float4 u1 = x0[lane + 32];
        float4 v0 = x1[lane];
        float4 v1 = x1[lane + 32];
        a0.x += u0.x; a0.y += u0.y; a0.z += u0.z; a0.w += u0.w;
        a1.x += u1.x; a1.y += u1.y; a1.z += u1.z; a1.w += u1.w;
        a0.x += v0.x; a0.y += v0.y; a0.z += v0.z; a0.w += v0.w;
        a1.x += v1.x; a1.y += v1.y; a1.z += v1.z; a1.w += v1.w;
    }
    if (e < end) {
        int s = csr[e];
        const float4* xs = (const float4*)(X + (size_t)s * DIM);
        float4 u0 = xs[lane];
        float4 u1 = xs[lane + 32];
        a0.x += u0.x; a0.y += u0.y; a0.z += u0.z; a0.w += u0.w;
        a1.x += u1.x; a1.y += u1.y; a1.z += u1.z; a1.w += u1.w;
    }
    float4* yr = (float4*)(Y + (size_t)w * DIM);
    yr[lane] = a0;
    yr[lane + 32] = a1;
}

// ------------------------------ fused conv ---------------------------------
// 64x256 tile, 8 warps (2M x 4N), warp tile 32x64, BK=16 DOUBLE-buffered W.

#define XP    260
#define XS_SZ (64 * XP)            // 16640 floats
#define WPAD  264
#define W_ST  (16 * WPAD)          // 4224 floats per chunk
#define CONV_SMEM_BYTES ((XS_SZ + 2 * W_ST) * 4)   // 100352 B -> 2 CTAs/SM

__device__ __forceinline__ float to_tf32(float x) {
    uint32_t u;
    asm("cvt.rna.tf32.f32 %0, %1;" : "=r"(u) : "f"(x));
    return __uint_as_float(u);
}

__device__ __forceinline__ void mma8(float* c, const uint32_t* a, const uint32_t* b) {
    asm volatile(
        "mma.sync.aligned.m16n8k8.row.col.f32.tf32.tf32.f32 "
        "{%0,%1,%2,%3},{%4,%5,%6,%7},{%8,%9},{%0,%1,%2,%3};\n"
        : "+f"(c[0]), "+f"(c[1]), "+f"(c[2]), "+f"(c[3])
        : "r"(a[0]), "r"(a[1]), "r"(a[2]), "r"(a[3]), "r"(b[0]), "r"(b[1]));
}

// C += XS(64x256 tf32) @ W(256x256); W via double-buffered BK=16 smem chunks.
// One __syncthreads per iteration: iteration 'it' stores into buffer (it+1)&1,
// whose previous readers (iteration it-1) all passed the barrier at end of it-1.
__device__ __forceinline__ void gemm_k256(
    const float* __restrict__ W, const float* XS, float* WS,
    float (&c)[2][8][4], int tid, int wm, int wn, int g, int tq) {
    const int wq = tid & 63;
    const int wkb = tid >> 6;          // 0..3
    float4 rw[4];
    #pragma unroll
    for (int i = 0; i < 4; ++i)
        rw[i] = *(const float4*)(W + (long)(wkb + i * 4) * 256 + wq * 4);
    #pragma unroll
    for (int i = 0; i < 4; ++i) {
        float4 v = rw[i];
        v.x = to_tf32(v.x); v.y = to_tf32(v.y);
        v.z = to_tf32(v.z); v.w = to_tf32(v.w);
        *(float4*)(WS + (wkb + i * 4) * WPAD + wq * 4) = v;
    }
    __syncthreads();
    #pragma unroll 1
    for (int it = 0; it < 16; ++it) {
        if (it < 15) {
            int k0 = (it + 1) * 16;
            #pragma unroll
            for (int i = 0; i < 4; ++i)
                rw[i] = *(const float4*)(W + (long)(k0 + wkb + i * 4) * 256 + wq * 4);
        }
        const float* ws = WS + (it & 1) * W_ST;
        #pragma unroll
        for (int kt = 0; kt < 2; ++kt) {
            int kb = it * 16 + kt * 8;
            int kw = kt * 8;
            uint32_t af[2][4], bf[8][2];
            #pragma unroll
            for (int mt = 0; mt < 2; ++mt) {
                int r0 = wm * 32 + mt * 16;
                af[mt][0] = __float_as_uint(XS[(r0 + g)     * XP + kb + tq]);
                af[mt][1] = __float_as_uint(XS[(r0 + 8 + g) * XP + kb + tq]);
                af[mt][2] = __float_as_uint(XS[(r0 + g)     * XP + kb + 4 + tq]);
                af[mt][3] = __float_as_uint(XS[(r0 + 8 + g) * XP + kb + 4 + tq]);
            }
            #pragma unroll
            for (int nt = 0; nt < 8; ++nt) {
                int n0 = wn * 64 + nt * 8;
                bf[nt][0] = __float_as_uint(ws[(kw + tq)     * WPAD + n0 + g]);
                bf[nt][1] = __float_as_uint(ws[(kw + 4 + tq) * WPAD + n0 + g]);
            }
            #pragma unroll
            for (int mt = 0; mt < 2; ++mt)
                #pragma unroll
                for (int nt = 0; nt < 8; ++nt)
                    mma8(c[mt][nt], af[mt], bf[nt]);
        }
        if (it < 15) {
            float* wsN = WS + ((it + 1) & 1) * W_ST;
            #pragma unroll
            for (int i = 0; i < 4; ++i) {
                float4 v = rw[i];
                v.x = to_tf32(v.x); v.y = to_tf32(v.y);
                v.z = to_tf32(v.z); v.w = to_tf32(v.w);
                *(float4*)(wsN + (wkb + i * 4) * WPAD + wq * 4) = v;
            }
            __syncthreads();
        }
    }
}

__global__ void __launch_bounds__(256, 2) k_conv(
    const float* __restrict__ A,   const float* __restrict__ bIn,
    const float* __restrict__ W1,  const float* __restrict__ b1,
    const float* __restrict__ lng, const float* __restrict__ lnb,
    const float* __restrict__ W2,  float* __restrict__ Out,
    int M, int reluLN, int hasG2) {
    extern __shared__ float sm[];
    float* XS = sm;
    float* WS = sm + XS_SZ;

    const int tid  = threadIdx.x;
    const int warp = tid >> 5, lane = tid & 31;
    const int wm = warp >> 2;
    const int wn = warp & 3;
    const int g  = lane >> 2;
    const int tq = lane & 3;
    const long blockRow = (long)blockIdx.x * 64;

    // ---- stage: XS = tf32( relu(A + bIn) ) ----
    #pragma unroll
    for (int i = 0; i < 16; ++i) {
        int id = i * 256 + tid;
        int row = id >> 6;
        int c4 = id & 63;
        long r = blockRow + row;
        if (r > M - 1) r = M - 1;
        float4 v = *(const float4*)(A + r * 256 + c4 * 4);
        float4 b = *(const float4*)(bIn + c4 * 4);
        v.x = to_tf32(fmaxf(v.x + b.x, 0.f));
        v.y = to_tf32(fmaxf(v.y + b.y, 0.f));
        v.z = to_tf32(fmaxf(v.z + b.z, 0.f));
        v.w = to_tf32(fmaxf(v.w + b.w, 0.f));
        *(float4*)(XS + row * XP + c4 * 4) = v;
    }
    // (gemm prologue's __syncthreads orders XS writes before reads)

    float c[2][8][4];
    #pragma unroll
    for (int i = 0; i < 2; ++i)
        #pragma unroll
        for (int j = 0; j < 8; ++j)
            #pragma unroll
            for (int k = 0; k < 4; ++k) c[i][j][k] = 0.f;

    gemm_k256(W1, XS, WS, c, tid, wm, wn, g, tq);

    // ---- epilogue 1: bias (+relu) -> XS fp32 ----
    __syncthreads();
    #pragma unroll
    for (int mt = 0; mt < 2; ++mt) {
        int r0 = wm * 32 + mt * 16;
        #pragma unroll
        for (int nt = 0; nt < 8; ++nt) {
            int col = wn * 64 + nt * 8 + tq * 2;
            float2 bv = *(const float2*)(b1 + col);
            float v0 = c[mt][nt][0] + bv.x;
            float v1 = c[mt][nt][1] + bv.y;
            float v2 = c[mt][nt][2] + bv.x;
            float v3 = c[mt][nt][3] + bv.y;
            if (reluLN) {
                v0 = fmaxf(v0, 0.f); v1 = fmaxf(v1, 0.f);
                v2 = fmaxf(v2, 0.f); v3 = fmaxf(v3, 0.f);
            }
            XS[(r0 + g)     * XP + col]     = v0;
            XS[(r0 + g)     * XP + col + 1] = v1;
            XS[(r0 + 8 + g) * XP + col]     = v2;
            XS[(r0 + 8 + g) * XP + col + 1] = v3;
        }
    }
    __syncthreads();

    // ---- LayerNorm: warp handles rows warp*8..warp*8+7 ----
    {
        float4 ga  = *(const float4*)(lng + lane * 8);
        float4 gb  = *(const float4*)(lng + lane * 8 + 4);
        float4 bta = *(const float4*)(lnb + lane * 8);
        float4 btb = *(const float4*)(lnb + lane * 8 + 4);
        #pragma unroll 1
        for (int i = 0; i < 8; ++i) {
            int row = warp * 8 + i;
            long grow = blockRow + row;
            float4 v0 = *(const float4*)(XS + row * XP + lane * 8);
            float4 v1 = *(const float4*)(XS + row * XP + lane * 8 + 4);
            float s  = v0.x + v0.y + v0.z + v0.w + v1.x + v1.y + v1.z + v1.w;
            float ss = v0.x * v0.x + v0.y * v0.y + v0.z * v0.z + v0.w * v0.w +
                       v1.x * v1.x + v1.y * v1.y + v1.z * v1.z + v1.w * v1.w;
            #pragma unroll
            for (int o = 16; o >= 1; o >>= 1) {
                s  += __shfl_xor_sync(0xffffffffu, s, o);
                ss += __shfl_xor_sync(0xffffffffu, ss, o);
            }
            float mean = s * (1.f / 256.f);
            float var  = ss * (1.f / 256.f) - mean * mean;
            float rstd = rsqrtf(var + 1e-5f);
            float4 o0, o1;
            o0.x = (v0.x - mean) * rstd * ga.x + bta.x;
            o0.y = (v0.y - mean) * rstd * ga.y + bta.y;
            o0.z = (v0.z - mean) * rstd * ga.z + bta.z;
            o0.w = (v0.w - mean) * rstd * ga.w + bta.w;
            o1.x = (v1.x - mean) * rstd * gb.x + btb.x;
            o1.y = (v1.y - mean) * rstd * gb.y + btb.y;
            o1.z = (v1.z - mean) * rstd * gb.z + btb.z;
            o1.w = (v1.w - mean) * rstd * gb.w + btb.w;
            if (hasG2) {
                o0.x = to_tf32(o0.x); o0.y = to_tf32(o0.y);
                o0.z = to_tf32(o0.z); o0.w = to_tf32(o0.w);
                o1.x = to_tf32(o1.x); o1.y = to_tf32(o1.y);
                o1.z = to_tf32(o1.z); o1.w = to_tf32(o1.w);
                *(float4*)(XS + row * XP + lane * 8)     = o0;
                *(float4*)(XS + row * XP + lane * 8 + 4) = o1;
            } else if (grow < M) {
                *(float4*)(Out + grow * 256 + lane * 8)     = o0;
                *(float4*)(Out + grow * 256 + lane * 8 + 4) = o1;
            }
        }
    }
    if (!hasG2) return;
    __syncthreads();

    // ---- GEMM2: u = h @ W2 (no bias) ----
    #pragma unroll
    for (int i = 0; i < 2; ++i)
        #pragma unroll
        for (int j = 0; j < 8; ++j)
            #pragma unroll
            for (int k = 0; k < 4; ++k) c[i][j][k] = 0.f;

    gemm_k256(W2, XS, WS, c, tid, wm, wn, g, tq);

    #pragma unroll
    for (int mt = 0; mt < 2; ++mt) {
        long rb = blockRow + wm * 32 + mt * 16;
        long r0 = rb + g;
        long r1 = rb + 8 + g;
        #pragma unroll
        for (int nt = 0; nt < 8; ++nt) {
            int col = wn * 64 + nt * 8 + tq * 2;
            if (r0 < M) {
                float2 t = {c[mt][nt][0], c[mt][nt][1]};
                *(float2*)(Out + r0 * 256 + col) = t;
            }
            if (r1 < M) {
                float2 t = {c[mt][nt][2], c[mt][nt][3]};
                *(float2*)(Out + r1 * 256 + col) = t;
            }
        }
    }
}

// --------------------------------- driver ---------------------------------

extern "C" void kernel_launch(void* const* d_in, const int* in_sizes, int n_in,
                              void* d_out, int out_size) {
    const int*   xcat = (const int*)d_in[0];
    const int*   ei   = (const int*)d_in[1];
    const float* e0   = (const float*)d_in[2];
    const float* e1   = (const float*)d_in[3];
    const float* e2   = (const float*)d_in[4];
    const float* e3   = (const float*)d_in[5];
    const float* w1a  = (const float*)d_in[6];
    const float* b1a  = (const float*)d_in[7];
    const float* w1b  = (const float*)d_in[8];
    const float* b1b  = (const float*)d_in[9];
    const float* w2a  = (const float*)d_in[10];
    const float* b2a  = (const float*)d_in[11];
    const float* w2b  = (const float*)d_in[12];
    const float* b2b  = (const float*)d_in[13];
    const float* ln1g = (const float*)d_in[14];
    const float* ln1b = (const float*)d_in[15];
    const float* ln2g = (const float*)d_in[16];
    const float* ln2b = (const float*)d_in[17];

    int M = in_sizes[0] / 4;
    int E = in_sizes[1] / 2;
    int V = in_sizes[2] / 64;

    float *b0, *b1, *tab;
    int *deg, *rowptr, *cursor, *csr;
    cudaGetSymbolAddress((void**)&b0, g_b0);
    cudaGetSymbolAddress((void**)&b1, g_b1);
    cudaGetSymbolAddress((void**)&tab, g_tab);
    cudaGetSymbolAddress((void**)&deg, g_deg);
    cudaGetSymbolAddress((void**)&rowptr, g_rowptr);
    cudaGetSymbolAddress((void**)&cursor, g_cursor);
    cudaGetSymbolAddress((void**)&csr, g_csr);

    cudaFuncSetAttribute(k_conv, cudaFuncAttributeMaxDynamicSharedMemorySize,
                         CONV_SMEM_BYTES);

    int rowGrid = (M + 7) / 8;
    int convGrid = (M + 63) / 64;

    // CSR by dst
    k_zero<<<(M + 255) / 256, 256>>>(deg, M);
    k_count<<<(E + 255) / 256, 256>>>(ei, deg, E);
    k_scan<<<1, 1024>>>(deg, rowptr, cursor, M);
    k_fill<<<(E + 255) / 256, 256>>>(ei, cursor, csr, E);

    // tables + z0
    dim3 tgrid((V + 15) / 16, 4);
    k_tab<<<tgrid, 256>>>(e0, e1, e2, e3, w1a, tab, V);
    k_z0<<<(M * 64 + 255) / 256, 256>>>(xcat, tab, b0, M);

    // conv1: a1 = agg(z0); h = LN1(relu(relu(a1+b1a)@W1b+b1b)); u = h@W2a
    k_agg<<<rowGrid, 256>>>(b0, b1, rowptr, csr, M);
    k_conv<<<convGrid, 256, CONV_SMEM_BYTES>>>(b1, b1a, w1b, b1b,
                                               ln1g, ln1b, w2a, b0, M, 1, 1);

    // conv2: a2 = agg(u); out = LN2(relu(a2+b2a)@W2b+b2b)
    k_agg<<<rowGrid, 256>>>(b0, b1, rowptr, csr, M);
    k_conv<<<convGrid, 256, CONV_SMEM_BYTES>>>(b1, b2a, w2b, b2b,
                                               ln2g, ln2b, nullptr,
                                               (float*)d_out, M, 0, 0);
}

// round 6
// speedup vs baseline: 1.6754x; 1.5327x over previous
#include <cuda_runtime.h>
#include <cuda_fp16.h>
#include <cstdint>

// ---------------------------------------------------------------------------
// CategoricalGINEncoder on GB300 (sm_103a) — round 6: fp16 datapath
//   T_f = emb_f @ W1a_f (fp32 tables); z0 = half(sum_f T_f[cat_f])
//   a1 = agg_h(z0); conv1: relu(+b1a)->@W1b(+b1b)->relu->LN1->@W2a -> u (half)
//   a2 = agg_h(u);  conv2: relu(+b2a)->@W2b(+b2b)->LN2 -> out (fp32)
//  GEMM: m16n8k16 f16 MMA, fp32 accum, ldmatrix A + ldmatrix.trans B,
//        64x256 tile, 8 warps (2Mx4N), BK=32 double-buffered W, 2 CTAs/SM.
//  LN: fully in-register via fragment reduction + tiny smem partials.
// ---------------------------------------------------------------------------

#define NMAX 100000
#define EMAX 1600000
#define DIM  256

__device__ __half g_h0[(size_t)NMAX * DIM];
__device__ __half g_h1[(size_t)NMAX * DIM];
__device__ float  g_tab[(size_t)4 * 1024 * DIM];
__device__ int    g_deg[NMAX];
__device__ int    g_rowptr[NMAX + 1];
__device__ int    g_cursor[NMAX];
__device__ int    g_csr[EMAX];

// ------------------------------- CSR build --------------------------------

__global__ void k_zero(int* __restrict__ p, int n) {
    int i = blockIdx.x * blockDim.x + threadIdx.x;
    if (i < n) p[i] = 0;
}

__global__ void k_count(const int* __restrict__ ei, int* __restrict__ deg, int E) {
    int e = blockIdx.x * blockDim.x + threadIdx.x;
    if (e < E) atomicAdd(&deg[ei[E + e]], 1);
}

__global__ void k_scan(const int* __restrict__ deg, int* __restrict__ rowptr,
                       int* __restrict__ cursor, int n) {
    __shared__ int sh[1024];
    int t = threadIdx.x;
    int chunk = (n + 1023) >> 10;
    int lo = t * chunk;
    int hi = min(lo + chunk, n);
    int s = 0;
    for (int i = lo; i < hi; ++i) s += deg[i];
    sh[t] = s;
    __syncthreads();
    for (int off = 1; off < 1024; off <<= 1) {
        int v = (t >= off) ? sh[t - off] : 0;
        __syncthreads();
        sh[t] += v;
        __syncthreads();
    }
    int run = (t == 0) ? 0 : sh[t - 1];
    for (int i = lo; i < hi; ++i) {
        rowptr[i] = run;
        cursor[i] = run;
        run += deg[i];
    }
    if (lo < n && hi == n) rowptr[n] = run;
}

__global__ void k_fill(const int* __restrict__ ei, int* __restrict__ cursor,
                       int* __restrict__ csr, int E) {
    int e = blockIdx.x * blockDim.x + threadIdx.x;
    if (e < E) {
        int s = ei[e];
        int d = ei[E + e];
        int p = atomicAdd(&cursor[d], 1);
        csr[p] = s;
    }
}

// ------------------------ embedding tables + z0 -----------------------------

__global__ void k_tab(const float* __restrict__ e0, const float* __restrict__ e1,
                      const float* __restrict__ e2, const float* __restrict__ e3,
                      const float* __restrict__ w1a, float* __restrict__ T, int V) {
    int f = blockIdx.y;
    const float* emb = (f == 0) ? e0 : (f == 1) ? e1 : (f == 2) ? e2 : e3;
    int v0 = blockIdx.x * 16;
    __shared__ float es[16 * 64];
    int tid = threadIdx.x;
    #pragma unroll
    for (int i = 0; i < 4; ++i) {
        int idx = i * 256 + tid;
        int v = idx >> 6, k = idx & 63;
        es[idx] = (v0 + v < V) ? emb[(v0 + v) * 64 + k] : 0.f;
    }
    __syncthreads();
    float acc[16];
    #pragma unroll
    for (int v = 0; v < 16; ++v) acc[v] = 0.f;
    int c = tid;
    #pragma unroll 4
    for (int k = 0; k < 64; ++k) {
        float w = w1a[(f * 64 + k) * 256 + c];
        #pragma unroll
        for (int v = 0; v < 16; ++v) acc[v] = fmaf(es[v * 64 + k], w, acc[v]);
    }
    #pragma unroll
    for (int v = 0; v < 16; ++v)
        if (v0 + v < V) T[((size_t)f * 1024 + v0 + v) * 256 + c] = acc[v];
}

__global__ void k_z0(const int* __restrict__ xc, const float* __restrict__ T,
                     __half* __restrict__ Z, int M) {
    int idx = blockIdx.x * blockDim.x + threadIdx.x;
    if (idx >= M * 32) return;
    int node = idx >> 5;
    int q = idx & 31;              // 8-col group
    int c0 = xc[node * 4 + 0];
    int c1 = xc[node * 4 + 1];
    int c2 = xc[node * 4 + 2];
    int c3 = xc[node * 4 + 3];
    const float* t0 = T + ((size_t)0 * 1024 + c0) * 256 + q * 8;
    const float* t1 = T + ((size_t)1 * 1024 + c1) * 256 + q * 8;
    const float* t2 = T + ((size_t)2 * 1024 + c2) * 256 + q * 8;
    const float* t3 = T + ((size_t)3 * 1024 + c3) * 256 + q * 8;
    float a[8];
    #pragma unroll
    for (int j = 0; j < 2; ++j) {
        float4 u0 = *(const float4*)(t0 + j * 4);
        float4 u1 = *(const float4*)(t1 + j * 4);
        float4 u2 = *(const float4*)(t2 + j * 4);
        float4 u3 = *(const float4*)(t3 + j * 4);
        a[j*4+0] = u0.x + u1.x + u2.x + u3.x;
        a[j*4+1] = u0.y + u1.y + u2.y + u3.y;
        a[j*4+2] = u0.z + u1.z + u2.z + u3.z;
        a[j*4+3] = u0.w + u1.w + u2.w + u3.w;
    }
    __half2 h0 = __floats2half2_rn(a[0], a[1]);
    __half2 h1 = __floats2half2_rn(a[2], a[3]);
    __half2 h2 = __floats2half2_rn(a[4], a[5]);
    __half2 h3 = __floats2half2_rn(a[6], a[7]);
    uint4 o;
    o.x = *(uint32_t*)&h0; o.y = *(uint32_t*)&h1;
    o.z = *(uint32_t*)&h2; o.w = *(uint32_t*)&h3;
    ((uint4*)(Z + (size_t)node * 256))[q] = o;
}

// --------------------------- aggregation (half) ----------------------------

__device__ __forceinline__ void addh8(float* a, uint4 v) {
    float2 f;
    f = __half22float2(*(__half2*)&v.x); a[0] += f.x; a[1] += f.y;
    f = __half22float2(*(__half2*)&v.y); a[2] += f.x; a[3] += f.y;
    f = __half22float2(*(__half2*)&v.z); a[4] += f.x; a[5] += f.y;
    f = __half22float2(*(__half2*)&v.w); a[6] += f.x; a[7] += f.y;
}

__global__ void k_agg(const __half* __restrict__ X, __half* __restrict__ Y,
                      const int* __restrict__ rowptr, const int* __restrict__ csr,
                      int M) {
    int w = (blockIdx.x * blockDim.x + threadIdx.x) >> 5;
    int lane = threadIdx.x & 31;
    if (w >= M) return;
    float a[8] = {0.f, 0.f, 0.f, 0.f, 0.f, 0.f, 0.f, 0.f};
    addh8(a, ((const uint4*)(X + (size_t)w * DIM))[lane]);
    int e = rowptr[w], end = rowptr[w + 1];
    for (; e + 1 < end; e += 2) {
        int s0 = csr[e];
        int s1 = csr[e + 1];
        uint4 u = ((const uint4*)(X + (size_t)s0 * DIM))[lane];
        uint4 v = ((const uint4*)(X + (size_t)s1 * DIM))[lane];
        addh8(a, u);
        addh8(a, v);
    }
    if (e < end) {
        int s = csr[e];
        addh8(a, ((const uint4*)(X + (size_t)s * DIM))[lane]);
    }
    __half2 h0 = __floats2half2_rn(a[0], a[1]);
    __half2 h1 = __floats2half2_rn(a[2], a[3]);
    __half2 h2 = __floats2half2_rn(a[4], a[5]);
    __half2 h3 = __floats2half2_rn(a[6], a[7]);
    uint4 o;
    o.x = *(uint32_t*)&h0; o.y = *(uint32_t*)&h1;
    o.z = *(uint32_t*)&h2; o.w = *(uint32_t*)&h3;
    ((uint4*)(Y + (size_t)w * DIM))[lane] = o;
}

// ------------------------------ fused conv ---------------------------------

#define XPH  264                    // XS row pitch (halves)
#define XS_H (64 * XPH)             // 16896 halves
#define WPH  264                    // W chunk row pitch (halves)
#define W_CH (32 * WPH)             // 8448 halves per chunk
#define CONV_SMEM_BYTES ((XS_H + 2 * W_CH) * 2 + 64 * 4 * 8)   // 69632 B

__device__ __forceinline__ void ldsm4(uint32_t* r, uint32_t addr) {
    asm volatile("ldmatrix.sync.aligned.m8n8.x4.shared.b16 {%0,%1,%2,%3},[%4];"
                 : "=r"(r[0]), "=r"(r[1]), "=r"(r[2]), "=r"(r[3]) : "r"(addr));
}
__device__ __forceinline__ void ldsm4t(uint32_t* r, uint32_t addr) {
    asm volatile("ldmatrix.sync.aligned.m8n8.x4.trans.shared.b16 {%0,%1,%2,%3},[%4];"
                 : "=r"(r[0]), "=r"(r[1]), "=r"(r[2]), "=r"(r[3]) : "r"(addr));
}
__device__ __forceinline__ void mma16(float* c, const uint32_t* a,
                                      uint32_t b0, uint32_t b1) {
    asm volatile(
        "mma.sync.aligned.m16n8k16.row.col.f32.f16.f16.f32 "
        "{%0,%1,%2,%3},{%4,%5,%6,%7},{%8,%9},{%0,%1,%2,%3};\n"
        : "+f"(c[0]), "+f"(c[1]), "+f"(c[2]), "+f"(c[3])
        : "r"(a[0]), "r"(a[1]), "r"(a[2]), "r"(a[3]), "r"(b0), "r"(b1));
}

// C += XS(64x256 f16) @ W(256x256 fp32->f16); BK=32 double-buffered W chunks.
__device__ __forceinline__ void gemm_h(
    const float* __restrict__ W, __half* WS,
    uint32_t xs_b, uint32_t ws_b,
    float (&c)[2][8][4], int tid, int wm, int wn, int lane) {
    const int kq = tid >> 6;                      // 0..3
    const int n4 = tid & 63;                      // float4 col slot
    const int aro = ((lane >> 3) & 1) * 8 + (lane & 7);
    const int kco = (lane >> 4) * 8;
    uint2 rw[8];
    #pragma unroll
    for (int i = 0; i < 8; ++i) {
        float4 w4 = *(const float4*)(W + (size_t)(kq + i * 4) * 256 + n4 * 4);
        __half2 p0 = __floats2half2_rn(w4.x, w4.y);
        __half2 p1 = __floats2half2_rn(w4.z, w4.w);
        rw[i] = make_uint2(*(uint32_t*)&p0, *(uint32_t*)&p1);
    }
    __syncthreads();                 // prior WS readers + XS stagers done
    #pragma unroll
    for (int i = 0; i < 8; ++i)
        *(uint2*)(WS + (kq + i * 4) * WPH + n4 * 4) = rw[i];
    __syncthreads();
    #pragma unroll 1
    for (int it = 0; it < 8; ++it) {
        if (it < 7) {
            const float* Wc = W + (size_t)(it + 1) * 32 * 256;
            #pragma unroll
            for (int i = 0; i < 8; ++i) {
                float4 w4 = *(const float4*)(Wc + (size_t)(kq + i * 4) * 256 + n4 * 4);
                __half2 p0 = __floats2half2_rn(w4.x, w4.y);
                __half2 p1 = __floats2half2_rn(w4.z, w4.w);
                rw[i] = make_uint2(*(uint32_t*)&p0, *(uint32_t*)&p1);
            }
        }
        uint32_t wsb = ws_b + (uint32_t)((it & 1) * W_CH * 2);
        #pragma unroll
        for (int kt = 0; kt < 2; ++kt) {
            const int ktb = it * 32 + kt * 16;    // k in XS
            const int ktL = kt * 16;              // k in chunk
            uint32_t a[2][4];
            #pragma unroll
            for (int mt = 0; mt < 2; ++mt)
                ldsm4(a[mt], xs_b +
                      2u * ((wm * 32 + mt * 16 + aro) * XPH + ktb + kco));
            #pragma unroll
            for (int hf = 0; hf < 2; ++hf) {
                uint32_t b[2][4];
                #pragma unroll
                for (int p = 0; p < 2; ++p) {
                    int np = hf * 2 + p;
                    ldsm4t(b[p], wsb +
                           2u * ((ktL + aro) * WPH + wn * 64 + np * 16 + kco));
                }
                #pragma unroll
                for (int mt = 0; mt < 2; ++mt)
                    #pragma unroll
                    for (int q = 0; q < 4; ++q)
                        mma16(c[mt][hf * 4 + q], a[mt],
                              b[q >> 1][(q & 1) * 2], b[q >> 1][(q & 1) * 2 + 1]);
            }
        }
        if (it < 7) {
            __half* wsN = WS + ((it + 1) & 1) * W_CH;
            #pragma unroll
            for (int i = 0; i < 8; ++i)
                *(uint2*)(wsN + (kq + i * 4) * WPH + n4 * 4) = rw[i];
            __syncthreads();
        }
    }
}

__global__ void __launch_bounds__(256, 2) k_conv(
    const __half* __restrict__ A,  const float* __restrict__ bIn,
    const float* __restrict__ W1,  const float* __restrict__ b1,
    const float* __restrict__ lng, const float* __restrict__ lnb,
    const float* __restrict__ W2,
    __half* __restrict__ OutH, float* __restrict__ OutF,
    int M, int reluLN, int hasG2) {
    extern __shared__ __half smh[];
    __half* XS = smh;
    __half* WS = smh + XS_H;
    float2* part = (float2*)(smh + XS_H + 2 * W_CH);   // [64][4]

    const int tid  = threadIdx.x;
    const int warp = tid >> 5, lane = tid & 31;
    const int wm = warp >> 2;
    const int wn = warp & 3;
    const int g  = lane >> 2;
    const int tq = lane & 3;
    const long blockRow = (long)blockIdx.x * 64;
    uint32_t xs_b = (uint32_t)__cvta_generic_to_shared(XS);
    uint32_t ws_b = (uint32_t)__cvta_generic_to_shared(WS);

    // ---- stage: XS = half( relu(A + bIn) ) ----
    #pragma unroll
    for (int i = 0; i < 8; ++i) {
        int id = i * 256 + tid;        // 2048 uint4 total
        int row = id >> 5;
        int q = id & 31;
        long r = blockRow + row;
        if (r > M - 1) r = M - 1;
        uint4 v = ((const uint4*)(A + r * 256))[q];
        float4 ba = *(const float4*)(bIn + q * 8);
        float4 bb = *(const float4*)(bIn + q * 8 + 4);
        float f[8];
        float2 t;
        t = __half22float2(*(__half2*)&v.x); f[0] = t.x; f[1] = t.y;
        t = __half22float2(*(__half2*)&v.y); f[2] = t.x; f[3] = t.y;
        t = __half22float2(*(__half2*)&v.z); f[4] = t.x; f[5] = t.y;
        t = __half22float2(*(__half2*)&v.w); f[6] = t.x; f[7] = t.y;
        f[0] = fmaxf(f[0] + ba.x, 0.f); f[1] = fmaxf(f[1] + ba.y, 0.f);
        f[2] = fmaxf(f[2] + ba.z, 0.f); f[3] = fmaxf(f[3] + ba.w, 0.f);
        f[4] = fmaxf(f[4] + bb.x, 0.f); f[5] = fmaxf(f[5] + bb.y, 0.f);
        f[6] = fmaxf(f[6] + bb.z, 0.f); f[7] = fmaxf(f[7] + bb.w, 0.f);
        __half2 h0 = __floats2half2_rn(f[0], f[1]);
        __half2 h1 = __floats2half2_rn(f[2], f[3]);
        __half2 h2 = __floats2half2_rn(f[4], f[5]);
        __half2 h3 = __floats2half2_rn(f[6], f[7]);
        uint4 o;
        o.x = *(uint32_t*)&h0; o.y = *(uint32_t*)&h1;
        o.z = *(uint32_t*)&h2; o.w = *(uint32_t*)&h3;
        *(uint4*)(XS + row * XPH + q * 8) = o;
    }

    float c[2][8][4];
    #pragma unroll
    for (int i = 0; i < 2; ++i)
        #pragma unroll
        for (int j = 0; j < 8; ++j)
            #pragma unroll
            for (int k = 0; k < 4; ++k) c[i][j][k] = 0.f;

    gemm_h(W1, WS, xs_b, ws_b, c, tid, wm, wn, lane);

    // ---- epilogue: bias (+relu) in regs ----
    #pragma unroll
    for (int mt = 0; mt < 2; ++mt)
        #pragma unroll
        for (int nt = 0; nt < 8; ++nt) {
            int col = wn * 64 + nt * 8 + tq * 2;
            float2 bv = *(const float2*)(b1 + col);
            c[mt][nt][0] += bv.x; c[mt][nt][1] += bv.y;
            c[mt][nt][2] += bv.x; c[mt][nt][3] += bv.y;
            if (reluLN) {
                c[mt][nt][0] = fmaxf(c[mt][nt][0], 0.f);
                c[mt][nt][1] = fmaxf(c[mt][nt][1], 0.f);
                c[mt][nt][2] = fmaxf(c[mt][nt][2], 0.f);
                c[mt][nt][3] = fmaxf(c[mt][nt][3], 0.f);
            }
        }

    // ---- LN: fragment reduction (4 row-contexts per thread) ----
    float s[2][2], ss[2][2];
    #pragma unroll
    for (int mt = 0; mt < 2; ++mt)
        #pragma unroll
        for (int hf = 0; hf < 2; ++hf) {
            float a = 0.f, b = 0.f;
            #pragma unroll
            for (int nt = 0; nt < 8; ++nt) {
                float v0 = c[mt][nt][hf * 2];
                float v1 = c[mt][nt][hf * 2 + 1];
                a += v0 + v1;
                b += v0 * v0 + v1 * v1;
            }
            #pragma unroll
            for (int o = 1; o <= 2; o <<= 1) {
                a += __shfl_xor_sync(0xffffffffu, a, o);
                b += __shfl_xor_sync(0xffffffffu, b, o);
            }
            s[mt][hf] = a;
            ss[mt][hf] = b;
        }
    if (tq == 0) {
        #pragma unroll
        for (int mt = 0; mt < 2; ++mt)
            #pragma unroll
            for (int hf = 0; hf < 2; ++hf) {
                int row = wm * 32 + mt * 16 + hf * 8 + g;
                part[row * 4 + wn] = make_float2(s[mt][hf], ss[mt][hf]);
            }
    }
    __syncthreads();   // also separates GEMM1's XS reads from XS writes below

    #pragma unroll
    for (int mt = 0; mt < 2; ++mt)
        #pragma unroll
        for (int hf = 0; hf < 2; ++hf) {
            int row = wm * 32 + mt * 16 + hf * 8 + g;
            float2 p0 = part[row * 4 + 0];
            float2 p1 = part[row * 4 + 1];
            float2 p2 = part[row * 4 + 2];
            float2 p3 = part[row * 4 + 3];
            float sum = p0.x + p1.x + p2.x + p3.x;
            float sq  = p0.y + p1.y + p2.y + p3.y;
            float mean = sum * (1.f / 256.f);
            float var  = sq * (1.f / 256.f) - mean * mean;
            float rstd = rsqrtf(var + 1e-5f);
            long grow = blockRow + row;
            #pragma unroll
            for (int nt = 0; nt < 8; ++nt) {
                int col = wn * 64 + nt * 8 + tq * 2;
                float2 gv = *(const float2*)(lng + col);
                float2 bv = *(const float2*)(lnb + col);
                float o0 = (c[mt][nt][hf * 2]     - mean) * rstd * gv.x + bv.x;
                float o1 = (c[mt][nt][hf * 2 + 1] - mean) * rstd * gv.y + bv.y;
                if (hasG2) {
                    __half2 h = __floats2half2_rn(o0, o1);
                    *(uint32_t*)(XS + row * XPH + col) = *(uint32_t*)&h;
                } else if (grow < M) {
                    float2 t = {o0, o1};
                    *(float2*)(OutF + grow * 256 + col) = t;
                }
            }
        }
    if (!hasG2) return;
    __syncthreads();   // XS writes visible before GEMM2 reads

    // ---- GEMM2: u = h @ W2 (no bias), store half ----
    #pragma unroll
    for (int i = 0; i < 2; ++i)
        #pragma unroll
        for (int j = 0; j < 8; ++j)
            #pragma unroll
            for (int k = 0; k < 4; ++k) c[i][j][k] = 0.f;

    gemm_h(W2, WS, xs_b, ws_b, c, tid, wm, wn, lane);

    #pragma unroll
    for (int mt = 0; mt < 2; ++mt) {
        long rb = blockRow + wm * 32 + mt * 16;
        long r0 = rb + g;
        long r1 = rb + 8 + g;
        #pragma unroll
        for (int nt = 0; nt < 8; ++nt) {
            int col = wn * 64 + nt * 8 + tq * 2;
            if (r0 < M) {
                __half2 h = __floats2half2_rn(c[mt][nt][0], c[mt][nt][1]);
                *(uint32_t*)(OutH + r0 * 256 + col) = *(uint32_t*)&h;
            }
            if (r1 < M) {
                __half2 h = __floats2half2_rn(c[mt][nt][2], c[mt][nt][3]);
                *(uint32_t*)(OutH + r1 * 256 + col) = *(uint32_t*)&h;
            }
        }
    }
}

// --------------------------------- driver ---------------------------------

extern "C" void kernel_launch(void* const* d_in, const int* in_sizes, int n_in,
                              void* d_out, int out_size) {
    const int*   xcat = (const int*)d_in[0];
    const int*   ei   = (const int*)d_in[1];
    const float* e0   = (const float*)d_in[2];
    const float* e1   = (const float*)d_in[3];
    const float* e2   = (const float*)d_in[4];
    const float* e3   = (const float*)d_in[5];
    const float* w1a  = (const float*)d_in[6];
    const float* b1a  = (const float*)d_in[7];
    const float* w1b  = (const float*)d_in[8];
    const float* b1b  = (const float*)d_in[9];
    const float* w2a  = (const float*)d_in[10];
    const float* b2a  = (const float*)d_in[11];
    const float* w2b  = (const float*)d_in[12];
    const float* b2b  = (const float*)d_in[13];
    const float* ln1g = (const float*)d_in[14];
    const float* ln1b = (const float*)d_in[15];
    const float* ln2g = (const float*)d_in[16];
    const float* ln2b = (const float*)d_in[17];

    int M = in_sizes[0] / 4;
    int E = in_sizes[1] / 2;
    int V = in_sizes[2] / 64;

    __half *h0, *h1;
    float *tab;
    int *deg, *rowptr, *cursor, *csr;
    cudaGetSymbolAddress((void**)&h0, g_h0);
    cudaGetSymbolAddress((void**)&h1, g_h1);
    cudaGetSymbolAddress((void**)&tab, g_tab);
    cudaGetSymbolAddress((void**)&deg, g_deg);
    cudaGetSymbolAddress((void**)&rowptr, g_rowptr);
    cudaGetSymbolAddress((void**)&cursor, g_cursor);
    cudaGetSymbolAddress((void**)&csr, g_csr);

    cudaFuncSetAttribute(k_conv, cudaFuncAttributeMaxDynamicSharedMemorySize,
                         CONV_SMEM_BYTES);

    int rowGrid = (M + 7) / 8;
    int convGrid = (M + 63) / 64;

    // CSR by dst
    k_zero<<<(M + 255) / 256, 256>>>(deg, M);
    k_count<<<(E + 255) / 256, 256>>>(ei, deg, E);
    k_scan<<<1, 1024>>>(deg, rowptr, cursor, M);
    k_fill<<<(E + 255) / 256, 256>>>(ei, cursor, csr, E);

    // tables + z0 (half)
    dim3 tgrid((V + 15) / 16, 4);
    k_tab<<<tgrid, 256>>>(e0, e1, e2, e3, w1a, tab, V);
    k_z0<<<(M * 32 + 255) / 256, 256>>>(xcat, tab, h0, M);

    // conv1: a1 = agg(z0); h = LN1(relu(relu(a1+b1a)@W1b+b1b)); u = h@W2a
    k_agg<<<rowGrid, 256>>>(h0, h1, rowptr, csr, M);
    k_conv<<<convGrid, 256, CONV_SMEM_BYTES>>>(h1, b1a, w1b, b1b, ln1g, ln1b,
                                               w2a, h0, nullptr, M, 1, 1);

    // conv2: a2 = agg(u); out = LN2(relu(a2+b2a)@W2b+b2b)
    k_agg<<<rowGrid, 256>>>(h0, h1, rowptr, csr, M);
    k_conv<<<convGrid, 256, CONV_SMEM_BYTES>>>(h1, b2a, w2b, b2b, ln2g, ln2b,
                                               nullptr, nullptr, (float*)d_out,
                                               M, 0, 0);
}

// round 7
// speedup vs baseline: 1.8007x; 1.0747x over previous
#include <cuda_runtime.h>
#include <cuda_fp16.h>
#include <cstdint>

// ---------------------------------------------------------------------------
// CategoricalGINEncoder on GB300 (sm_103a) — round 7
//  round 6 (fp16 datapath) +
//   - weights pre-converted to half once (halves W L2 traffic, removes cvt
//     from GEMM hot loop)
//   - half embedding tables (halves z0 gather traffic)
//   - memset-node zero + int4-vectorized CSR count/fill
// ---------------------------------------------------------------------------

#define NMAX 100000
#define EMAX 1600000
#define DIM  256

__device__ __half g_h0[(size_t)NMAX * DIM];
__device__ __half g_h1[(size_t)NMAX * DIM];
__device__ __half g_tabh[(size_t)4 * 1024 * DIM];
__device__ __half g_w1b[DIM * DIM];
__device__ __half g_w2a[DIM * DIM];
__device__ __half g_w2b[DIM * DIM];
__device__ int    g_deg[NMAX];
__device__ int    g_rowptr[NMAX + 1];
__device__ int    g_cursor[NMAX];
__device__ int    g_csr[EMAX];

// --------------------------- weight conversion ------------------------------

__global__ void k_cvt(const float* __restrict__ src, __half* __restrict__ dst,
                      int n) {
    int i = (blockIdx.x * blockDim.x + threadIdx.x) * 8;
    if (i >= n) return;
    float4 a = *(const float4*)(src + i);
    float4 b = *(const float4*)(src + i + 4);
    __half2 h0 = __floats2half2_rn(a.x, a.y);
    __half2 h1 = __floats2half2_rn(a.z, a.w);
    __half2 h2 = __floats2half2_rn(b.x, b.y);
    __half2 h3 = __floats2half2_rn(b.z, b.w);
    uint4 o;
    o.x = *(uint32_t*)&h0; o.y = *(uint32_t*)&h1;
    o.z = *(uint32_t*)&h2; o.w = *(uint32_t*)&h3;
    *(uint4*)(dst + i) = o;
}

// ------------------------------- CSR build --------------------------------

__global__ void k_count4(const int* __restrict__ ei, int* __restrict__ deg,
                         int E) {
    int i = (blockIdx.x * blockDim.x + threadIdx.x) * 4;
    if (i >= E) return;
    if (i + 3 < E) {
        int4 d = *(const int4*)(ei + E + i);
        atomicAdd(&deg[d.x], 1);
        atomicAdd(&deg[d.y], 1);
        atomicAdd(&deg[d.z], 1);
        atomicAdd(&deg[d.w], 1);
    } else {
        for (; i < E; ++i) atomicAdd(&deg[ei[E + i]], 1);
    }
}

__global__ void k_scan(const int* __restrict__ deg, int* __restrict__ rowptr,
                       int* __restrict__ cursor, int n) {
    __shared__ int sh[1024];
    int t = threadIdx.x;
    int chunk = (n + 1023) >> 10;
    int lo = t * chunk;
    int hi = min(lo + chunk, n);
    int s = 0;
    for (int i = lo; i < hi; ++i) s += deg[i];
    sh[t] = s;
    __syncthreads();
    for (int off = 1; off < 1024; off <<= 1) {
        int v = (t >= off) ? sh[t - off] : 0;
        __syncthreads();
        sh[t] += v;
        __syncthreads();
    }
    int run = (t == 0) ? 0 : sh[t - 1];
    for (int i = lo; i < hi; ++i) {
        rowptr[i] = run;
        cursor[i] = run;
        run += deg[i];
    }
    if (lo < n && hi == n) rowptr[n] = run;
}

__global__ void k_fill4(const int* __restrict__ ei, int* __restrict__ cursor,
                        int* __restrict__ csr, int E) {
    int i = (blockIdx.x * blockDim.x + threadIdx.x) * 4;
    if (i >= E) return;
    if (i + 3 < E) {
        int4 s = *(const int4*)(ei + i);
        int4 d = *(const int4*)(ei + E + i);
        csr[atomicAdd(&cursor[d.x], 1)] = s.x;
        csr[atomicAdd(&cursor[d.y], 1)] = s.y;
        csr[atomicAdd(&cursor[d.z], 1)] = s.z;
        csr[atomicAdd(&cursor[d.w], 1)] = s.w;
    } else {
        for (; i < E; ++i)
            csr[atomicAdd(&cursor[ei[E + i]], 1)] = ei[i];
    }
}

// ------------------------ embedding tables + z0 -----------------------------

__global__ void k_tab(const float* __restrict__ e0, const float* __restrict__ e1,
                      const float* __restrict__ e2, const float* __restrict__ e3,
                      const float* __restrict__ w1a, __half* __restrict__ T,
                      int V) {
    int f = blockIdx.y;
    const float* emb = (f == 0) ? e0 : (f == 1) ? e1 : (f == 2) ? e2 : e3;
    int v0 = blockIdx.x * 16;
    __shared__ float es[16 * 64];
    int tid = threadIdx.x;
    #pragma unroll
    for (int i = 0; i < 4; ++i) {
        int idx = i * 256 + tid;
        int v = idx >> 6, k = idx & 63;
        es[idx] = (v0 + v < V) ? emb[(v0 + v) * 64 + k] : 0.f;
    }
    __syncthreads();
    float acc[16];
    #pragma unroll
    for (int v = 0; v < 16; ++v) acc[v] = 0.f;
    int c = tid;
    #pragma unroll 4
    for (int k = 0; k < 64; ++k) {
        float w = w1a[(f * 64 + k) * 256 + c];
        #pragma unroll
        for (int v = 0; v < 16; ++v) acc[v] = fmaf(es[v * 64 + k], w, acc[v]);
    }
    #pragma unroll
    for (int v = 0; v < 16; ++v)
        if (v0 + v < V)
            T[((size_t)f * 1024 + v0 + v) * 256 + c] = __float2half_rn(acc[v]);
}

__device__ __forceinline__ void addh8(float* a, uint4 v) {
    float2 f;
    f = __half22float2(*(__half2*)&v.x); a[0] += f.x; a[1] += f.y;
    f = __half22float2(*(__half2*)&v.y); a[2] += f.x; a[3] += f.y;
    f = __half22float2(*(__half2*)&v.z); a[4] += f.x; a[5] += f.y;
    f = __half22float2(*(__half2*)&v.w); a[6] += f.x; a[7] += f.y;
}

__global__ void k_z0(const int* __restrict__ xc, const __half* __restrict__ T,
                     __half* __restrict__ Z, int M) {
    int idx = blockIdx.x * blockDim.x + threadIdx.x;
    if (idx >= M * 32) return;
    int node = idx >> 5;
    int q = idx & 31;              // 8-col group
    int c0 = xc[node * 4 + 0];
    int c1 = xc[node * 4 + 1];
    int c2 = xc[node * 4 + 2];
    int c3 = xc[node * 4 + 3];
    float a[8] = {0.f, 0.f, 0.f, 0.f, 0.f, 0.f, 0.f, 0.f};
    addh8(a, *(const uint4*)(T + ((size_t)0 * 1024 + c0) * 256 + q * 8));
    addh8(a, *(const uint4*)(T + ((size_t)1 * 1024 + c1) * 256 + q * 8));
    addh8(a, *(const uint4*)(T + ((size_t)2 * 1024 + c2) * 256 + q * 8));
    addh8(a, *(const uint4*)(T + ((size_t)3 * 1024 + c3) * 256 + q * 8));
    __half2 h0 = __floats2half2_rn(a[0], a[1]);
    __half2 h1 = __floats2half2_rn(a[2], a[3]);
    __half2 h2 = __floats2half2_rn(a[4], a[5]);
    __half2 h3 = __floats2half2_rn(a[6], a[7]);
    uint4 o;
    o.x = *(uint32_t*)&h0; o.y = *(uint32_t*)&h1;
    o.z = *(uint32_t*)&h2; o.w = *(uint32_t*)&h3;
    ((uint4*)(Z + (size_t)node * 256))[q] = o;
}

// --------------------------- aggregation (half) ----------------------------

__global__ void k_agg(const __half* __restrict__ X, __half* __restrict__ Y,
                      const int* __restrict__ rowptr, const int* __restrict__ csr,
                      int M) {
    int w = (blockIdx.x * blockDim.x + threadIdx.x) >> 5;
    int lane = threadIdx.x & 31;
    if (w >= M) return;
    float a[8] = {0.f, 0.f, 0.f, 0.f, 0.f, 0.f, 0.f, 0.f};
    addh8(a, ((const uint4*)(X + (size_t)w * DIM))[lane]);
    int e = rowptr[w], end = rowptr[w + 1];
    for (; e + 1 < end; e += 2) {
        int s0 = csr[e];
        int s1 = csr[e + 1];
        uint4 u = ((const uint4*)(X + (size_t)s0 * DIM))[lane];
        uint4 v = ((const uint4*)(X + (size_t)s1 * DIM))[lane];
        addh8(a, u);
        addh8(a, v);
    }
    if (e < end) {
        int s = csr[e];
        addh8(a, ((const uint4*)(X + (size_t)s * DIM))[lane]);
    }
    __half2 h0 = __floats2half2_rn(a[0], a[1]);
    __half2 h1 = __floats2half2_rn(a[2], a[3]);
    __half2 h2 = __floats2half2_rn(a[4], a[5]);
    __half2 h3 = __floats2half2_rn(a[6], a[7]);
    uint4 o;
    o.x = *(uint32_t*)&h0; o.y = *(uint32_t*)&h1;
    o.z = *(uint32_t*)&h2; o.w = *(uint32_t*)&h3;
    ((uint4*)(Y + (size_t)w * DIM))[lane] = o;
}

// ------------------------------ fused conv ---------------------------------

#define XPH  264                    // XS row pitch (halves)
#define XS_H (64 * XPH)             // 16896 halves
#define WPH  264                    // W chunk row pitch (halves)
#define W_CH (32 * WPH)             // 8448 halves per chunk
#define CONV_SMEM_BYTES ((XS_H + 2 * W_CH) * 2 + 64 * 4 * 8)   // 69632 B

__device__ __forceinline__ void ldsm4(uint32_t* r, uint32_t addr) {
    asm volatile("ldmatrix.sync.aligned.m8n8.x4.shared.b16 {%0,%1,%2,%3},[%4];"
                 : "=r"(r[0]), "=r"(r[1]), "=r"(r[2]), "=r"(r[3]) : "r"(addr));
}
__device__ __forceinline__ void ldsm4t(uint32_t* r, uint32_t addr) {
    asm volatile("ldmatrix.sync.aligned.m8n8.x4.trans.shared.b16 {%0,%1,%2,%3},[%4];"
                 : "=r"(r[0]), "=r"(r[1]), "=r"(r[2]), "=r"(r[3]) : "r"(addr));
}
__device__ __forceinline__ void mma16(float* c, const uint32_t* a,
                                      uint32_t b0, uint32_t b1) {
    asm volatile(
        "mma.sync.aligned.m16n8k16.row.col.f32.f16.f16.f32 "
        "{%0,%1,%2,%3},{%4,%5,%6,%7},{%8,%9},{%0,%1,%2,%3};\n"
        : "+f"(c[0]), "+f"(c[1]), "+f"(c[2]), "+f"(c[3])
        : "r"(a[0]), "r"(a[1]), "r"(a[2]), "r"(a[3]), "r"(b0), "r"(b1));
}

// C += XS(64x256 f16) @ W(256x256 f16); BK=32 double-buffered W chunks.
__device__ __forceinline__ void gemm_h(
    const __half* __restrict__ W, __half* WS,
    uint32_t xs_b, uint32_t ws_b,
    float (&c)[2][8][4], int tid, int wm, int wn, int lane) {
    const int krow = tid >> 5;                    // 0..7
    const int n8 = tid & 31;                      // 8-half col slot
    const int aro = ((lane >> 3) & 1) * 8 + (lane & 7);
    const int kco = (lane >> 4) * 8;
    uint4 rw[4];
    #pragma unroll
    for (int i = 0; i < 4; ++i)
        rw[i] = *(const uint4*)(W + (size_t)(krow + i * 8) * 256 + n8 * 8);
    __syncthreads();                 // prior WS readers + XS stagers done
    #pragma unroll
    for (int i = 0; i < 4; ++i)
        *(uint4*)(WS + (krow + i * 8) * WPH + n8 * 8) = rw[i];
    __syncthreads();
    #pragma unroll 1
    for (int it = 0; it < 8; ++it) {
        if (it < 7) {
            const __half* Wc = W + (size_t)(it + 1) * 32 * 256;
            #pragma unroll
            for (int i = 0; i < 4; ++i)
                rw[i] = *(const uint4*)(Wc + (size_t)(krow + i * 8) * 256 + n8 * 8);
        }
        uint32_t wsb = ws_b + (uint32_t)((it & 1) * W_CH * 2);
        #pragma unroll
        for (int kt = 0; kt < 2; ++kt) {
            const int ktb = it * 32 + kt * 16;    // k in XS
            const int ktL = kt * 16;              // k in chunk
            uint32_t a[2][4];
            #pragma unroll
            for (int mt = 0; mt < 2; ++mt)
                ldsm4(a[mt], xs_b +
                      2u * ((wm * 32 + mt * 16 + aro) * XPH + ktb + kco));
            #pragma unroll
            for (int hf = 0; hf < 2; ++hf) {
                uint32_t b[2][4];
                #pragma unroll
                for (int p = 0; p < 2; ++p) {
                    int np = hf * 2 + p;
                    ldsm4t(b[p], wsb +
                           2u * ((ktL + aro) * WPH + wn * 64 + np * 16 + kco));
                }
                #pragma unroll
                for (int mt = 0; mt < 2; ++mt)
                    #pragma unroll
                    for (int q = 0; q < 4; ++q)
                        mma16(c[mt][hf * 4 + q], a[mt],
                              b[q >> 1][(q & 1) * 2], b[q >> 1][(q & 1) * 2 + 1]);
            }
        }
        if (it < 7) {
            __half* wsN = WS + ((it + 1) & 1) * W_CH;
            #pragma unroll
            for (int i = 0; i < 4; ++i)
                *(uint4*)(wsN + (krow + i * 8) * WPH + n8 * 8) = rw[i];
            __syncthreads();
        }
    }
}

__global__ void __launch_bounds__(256, 2) k_conv(
    const __half* __restrict__ A,  const float* __restrict__ bIn,
    const __half* __restrict__ W1, const float* __restrict__ b1,
    const float* __restrict__ lng, const float* __restrict__ lnb,
    const __half* __restrict__ W2,
    __half* __restrict__ OutH, float* __restrict__ OutF,
    int M, int reluLN, int hasG2) {
    extern __shared__ __half smh[];
    __half* XS = smh;
    __half* WS = smh + XS_H;
    float2* part = (float2*)(smh + XS_H + 2 * W_CH);   // [64][4]

    const int tid  = threadIdx.x;
    const int warp = tid >> 5, lane = tid & 31;
    const int wm = warp >> 2;
    const int wn = warp & 3;
    const int g  = lane >> 2;
    const int tq = lane & 3;
    const long blockRow = (long)blockIdx.x * 64;
    uint32_t xs_b = (uint32_t)__cvta_generic_to_shared(XS);
    uint32_t ws_b = (uint32_t)__cvta_generic_to_shared(WS);

    // ---- stage: XS = half( relu(A + bIn) ) ----
    #pragma unroll
    for (int i = 0; i < 8; ++i) {
        int id = i * 256 + tid;        // 2048 uint4 total
        int row = id >> 5;
        int q = id & 31;
        long r = blockRow + row;
        if (r > M - 1) r = M - 1;
        uint4 v = ((const uint4*)(A + r * 256))[q];
        float4 ba = *(const float4*)(bIn + q * 8);
        float4 bb = *(const float4*)(bIn + q * 8 + 4);
        float f[8];
        float2 t;
        t = __half22float2(*(__half2*)&v.x); f[0] = t.x; f[1] = t.y;
        t = __half22float2(*(__half2*)&v.y); f[2] = t.x; f[3] = t.y;
        t = __half22float2(*(__half2*)&v.z); f[4] = t.x; f[5] = t.y;
        t = __half22float2(*(__half2*)&v.w); f[6] = t.x; f[7] = t.y;
        f[0] = fmaxf(f[0] + ba.x, 0.f); f[1] = fmaxf(f[1] + ba.y, 0.f);
        f[2] = fmaxf(f[2] + ba.z, 0.f); f[3] = fmaxf(f[3] + ba.w, 0.f);
        f[4] = fmaxf(f[4] + bb.x, 0.f); f[5] = fmaxf(f[5] + bb.y, 0.f);
        f[6] = fmaxf(f[6] + bb.z, 0.f); f[7] = fmaxf(f[7] + bb.w, 0.f);
        __half2 h0 = __floats2half2_rn(f[0], f[1]);
        __half2 h1 = __floats2half2_rn(f[2], f[3]);
        __half2 h2 = __floats2half2_rn(f[4], f[5]);
        __half2 h3 = __floats2half2_rn(f[6], f[7]);
        uint4 o;
        o.x = *(uint32_t*)&h0; o.y = *(uint32_t*)&h1;
        o.z = *(uint32_t*)&h2; o.w = *(uint32_t*)&h3;
        *(uint4*)(XS + row * XPH + q * 8) = o;
    }

    float c[2][8][4];
    #pragma unroll
    for (int i = 0; i < 2; ++i)
        #pragma unroll
        for (int j = 0; j < 8; ++j)
            #pragma unroll
            for (int k = 0; k < 4; ++k) c[i][j][k] = 0.f;

    gemm_h(W1, WS, xs_b, ws_b, c, tid, wm, wn, lane);

    // ---- epilogue: bias (+relu) in regs ----
    #pragma unroll
    for (int mt = 0; mt < 2; ++mt)
        #pragma unroll
        for (int nt = 0; nt < 8; ++nt) {
            int col = wn * 64 + nt * 8 + tq * 2;
            float2 bv = *(const float2*)(b1 + col);
            c[mt][nt][0] += bv.x; c[mt][nt][1] += bv.y;
            c[mt][nt][2] += bv.x; c[mt][nt][3] += bv.y;
            if (reluLN) {
                c[mt][nt][0] = fmaxf(c[mt][nt][0], 0.f);
                c[mt][nt][1] = fmaxf(c[mt][nt][1], 0.f);
                c[mt][nt][2] = fmaxf(c[mt][nt][2], 0.f);
                c[mt][nt][3] = fmaxf(c[mt][nt][3], 0.f);
            }
        }

    // ---- LN: fragment reduction ----
    float s[2][2], ss[2][2];
    #pragma unroll
    for (int mt = 0; mt < 2; ++mt)
        #pragma unroll
        for (int hf = 0; hf < 2; ++hf) {
            float a = 0.f, b = 0.f;
            #pragma unroll
            for (int nt = 0; nt < 8; ++nt) {
                float v0 = c[mt][nt][hf * 2];
                float v1 = c[mt][nt][hf * 2 + 1];
                a += v0 + v1;
                b += v0 * v0 + v1 * v1;
            }
            #pragma unroll
            for (int o = 1; o <= 2; o <<= 1) {
                a += __shfl_xor_sync(0xffffffffu, a, o);
                b += __shfl_xor_sync(0xffffffffu, b, o);
            }
            s[mt][hf] = a;
            ss[mt][hf] = b;
        }
    if (tq == 0) {
        #pragma unroll
        for (int mt = 0; mt < 2; ++mt)
            #pragma unroll
            for (int hf = 0; hf < 2; ++hf) {
                int row = wm * 32 + mt * 16 + hf * 8 + g;
                part[row * 4 + wn] = make_float2(s[mt][hf], ss[mt][hf]);
            }
    }
    __syncthreads();   // also separates GEMM1's XS reads from XS writes below

    #pragma unroll
    for (int mt = 0; mt < 2; ++mt)
        #pragma unroll
        for (int hf = 0; hf < 2; ++hf) {
            int row = wm * 32 + mt * 16 + hf * 8 + g;
            float2 p0 = part[row * 4 + 0];
            float2 p1 = part[row * 4 + 1];
            float2 p2 = part[row * 4 + 2];
            float2 p3 = part[row * 4 + 3];
            float sum = p0.x + p1.x + p2.x + p3.x;
            float sq  = p0.y + p1.y + p2.y + p3.y;
            float mean = sum * (1.f / 256.f);
            float var  = sq * (1.f / 256.f) - mean * mean;
            float rstd = rsqrtf(var + 1e-5f);
            long grow = blockRow + row;
            #pragma unroll
            for (int nt = 0; nt < 8; ++nt) {
                int col = wn * 64 + nt * 8 + tq * 2;
                float2 gv = *(const float2*)(lng + col);
                float2 bv = *(const float2*)(lnb + col);
                float o0 = (c[mt][nt][hf * 2]     - mean) * rstd * gv.x + bv.x;
                float o1 = (c[mt][nt][hf * 2 + 1] - mean) * rstd * gv.y + bv.y;
                if (hasG2) {
                    __half2 h = __floats2half2_rn(o0, o1);
                    *(uint32_t*)(XS + row * XPH + col) = *(uint32_t*)&h;
                } else if (grow < M) {
                    float2 t = {o0, o1};
                    *(float2*)(OutF + grow * 256 + col) = t;
                }
            }
        }
    if (!hasG2) return;
    __syncthreads();   // XS writes visible before GEMM2 reads

    // ---- GEMM2: u = h @ W2 (no bias), store half ----
    #pragma unroll
    for (int i = 0; i < 2; ++i)
        #pragma unroll
        for (int j = 0; j < 8; ++j)
            #pragma unroll
            for (int k = 0; k < 4; ++k) c[i][j][k] = 0.f;

    gemm_h(W2, WS, xs_b, ws_b, c, tid, wm, wn, lane);

    #pragma unroll
    for (int mt = 0; mt < 2; ++mt) {
        long rb = blockRow + wm * 32 + mt * 16;
        long r0 = rb + g;
        long r1 = rb + 8 + g;
        #pragma unroll
        for (int nt = 0; nt < 8; ++nt) {
            int col = wn * 64 + nt * 8 + tq * 2;
            if (r0 < M) {
                __half2 h = __floats2half2_rn(c[mt][nt][0], c[mt][nt][1]);
                *(uint32_t*)(OutH + r0 * 256 + col) = *(uint32_t*)&h;
            }
            if (r1 < M) {
                __half2 h = __floats2half2_rn(c[mt][nt][2], c[mt][nt][3]);
                *(uint32_t*)(OutH + r1 * 256 + col) = *(uint32_t*)&h;
            }
        }
    }
}

// --------------------------------- driver ---------------------------------

extern "C" void kernel_launch(void* const* d_in, const int* in_sizes, int n_in,
                              void* d_out, int out_size) {
    const int*   xcat = (const int*)d_in[0];
    const int*   ei   = (const int*)d_in[1];
    const float* e0   = (const float*)d_in[2];
    const float* e1   = (const float*)d_in[3];
    const float* e2   = (const float*)d_in[4];
    const float* e3   = (const float*)d_in[5];
    const float* w1a  = (const float*)d_in[6];
    const float* b1a  = (const float*)d_in[7];
    const float* w1b  = (const float*)d_in[8];
    const float* b1b  = (const float*)d_in[9];
    const float* w2a  = (const float*)d_in[10];
    const float* b2a  = (const float*)d_in[11];
    const float* w2b  = (const float*)d_in[12];
    const float* b2b  = (const float*)d_in[13];
    const float* ln1g = (const float*)d_in[14];
    const float* ln1b = (const float*)d_in[15];
    const float* ln2g = (const float*)d_in[16];
    const float* ln2b = (const float*)d_in[17];

    int M = in_sizes[0] / 4;
    int E = in_sizes[1] / 2;
    int V = in_sizes[2] / 64;

    __half *h0, *h1, *tabh, *hw1b, *hw2a, *hw2b;
    int *deg, *rowptr, *cursor, *csr;
    cudaGetSymbolAddress((void**)&h0, g_h0);
    cudaGetSymbolAddress((void**)&h1, g_h1);
    cudaGetSymbolAddress((void**)&tabh, g_tabh);
    cudaGetSymbolAddress((void**)&hw1b, g_w1b);
    cudaGetSymbolAddress((void**)&hw2a, g_w2a);
    cudaGetSymbolAddress((void**)&hw2b, g_w2b);
    cudaGetSymbolAddress((void**)&deg, g_deg);
    cudaGetSymbolAddress((void**)&rowptr, g_rowptr);
    cudaGetSymbolAddress((void**)&cursor, g_cursor);
    cudaGetSymbolAddress((void**)&csr, g_csr);

    cudaFuncSetAttribute(k_conv, cudaFuncAttributeMaxDynamicSharedMemorySize,
                         CONV_SMEM_BYTES);

    int rowGrid = (M + 7) / 8;
    int convGrid = (M + 63) / 64;

    // weights -> half (once per call; cheap)
    k_cvt<<<(DIM * DIM / 8 + 255) / 256, 256>>>(w1b, hw1b, DIM * DIM);
    k_cvt<<<(DIM * DIM / 8 + 255) / 256, 256>>>(w2a, hw2a, DIM * DIM);
    k_cvt<<<(DIM * DIM / 8 + 255) / 256, 256>>>(w2b, hw2b, DIM * DIM);

    // CSR by dst
    cudaMemsetAsync(deg, 0, (size_t)M * sizeof(int), 0);
    k_count4<<<(E / 4 + 255) / 256, 256>>>(ei, deg, E);
    k_scan<<<1, 1024>>>(deg, rowptr, cursor, M);
    k_fill4<<<(E / 4 + 255) / 256, 256>>>(ei, cursor, csr, E);

    // tables (half) + z0 (half)
    dim3 tgrid((V + 15) / 16, 4);
    k_tab<<<tgrid, 256>>>(e0, e1, e2, e3, w1a, tabh, V);
    k_z0<<<(M * 32 + 255) / 256, 256>>>(xcat, tabh, h0, M);

    // conv1: a1 = agg(z0); h = LN1(relu(relu(a1+b1a)@W1b+b1b)); u = h@W2a
    k_agg<<<rowGrid, 256>>>(h0, h1, rowptr, csr, M);
    k_conv<<<convGrid, 256, CONV_SMEM_BYTES>>>(h1, b1a, hw1b, b1b, ln1g, ln1b,
                                               hw2a, h0, nullptr, M, 1, 1);

    // conv2: a2 = agg(u); out = LN2(relu(a2+b2a)@W2b+b2b)
    k_agg<<<rowGrid, 256>>>(h0, h1, rowptr, csr, M);
    k_conv<<<convGrid, 256, CONV_SMEM_BYTES>>>(h1, b2a, hw2b, b2b, ln2g, ln2b,
                                               nullptr, nullptr, (float*)d_out,
                                               M, 0, 0);
}